// round 15
// baseline (speedup 1.0000x reference)
#include <cuda_runtime.h>
#include <cuda_bf16.h>
#include <math.h>
#include <stdint.h>

// ---------------- problem constants ----------------
constexpr int   BN      = 8192;
constexpr int   DD      = 256;
constexpr int   NS      = 64;
constexpr float INV_TAU = 1.0f / 0.07f;
constexpr float MARGIN  = 0.2f;
constexpr int   CAP     = 192;      // max rows per species (128 + ~6 sigma)

// ---------------- device scratch ----------------
__device__ __align__(16) __nv_bfloat16 g_Abf[(size_t)BN * DD];
__device__ __align__(16) __nv_bfloat16 g_Bbf[(size_t)BN * DD];

__device__ float g_diag[BN];
__device__ int   g_cnti[NS];
__device__ int   g_off[NS];
__device__ int   g_fill[NS];
__device__ int   g_perm[BN];
__device__ float g_Tall[DD];

__device__ float g_per[NS];    // per-species infonce contribution
__device__ float g_pern[NS];   // per-species valid flag
__device__ float g_triv[NS];   // per-species triplet sum
__device__ float g_trin[NS];   // per-species triplet count
__device__ int   g_done;

// ---------------- setup: histogram + offsets (1 block) ----------------
__global__ void setup_kernel(const int* __restrict__ ids) {
    __shared__ int hist[NS];
    const int tid = threadIdx.x;         // 1024 threads
    if (tid < NS) hist[tid] = 0;
    __syncthreads();
    #pragma unroll
    for (int t = 0; t < BN / 1024; t++)
        atomicAdd(&hist[ids[tid + t * 1024]], 1);
    __syncthreads();
    if (tid == 0) {
        int run = 0;
        for (int c = 0; c < NS; c++) {
            g_off[c] = run;
            g_cnti[c] = hist[c];
            run += hist[c];
        }
        g_done = 0;
    }
    if (tid < NS) g_fill[tid] = 0;
    if (tid < DD) g_Tall[tid] = 0.f;
}

// ---------------- prep: fp32->bf16, exact diag, scatter, Tall ----------------
__global__ void prep_kernel(const float* __restrict__ S,
                            const float* __restrict__ T,
                            const int* __restrict__ ids) {
    __shared__ float sh_tall[DD];
    const int tid  = threadIdx.x;
    const int warp = tid >> 5;
    const int lane = tid & 31;
    const int row  = blockIdx.x * 8 + warp;
    if (tid < DD) sh_tall[tid] = 0.f;
    __syncthreads();

    const float4* s4 = (const float4*)(S + (size_t)row * DD);
    const float4* t4 = (const float4*)(T + (size_t)row * DD);
    float4 s0 = s4[lane * 2], s1 = s4[lane * 2 + 1];
    float4 t0 = t4[lane * 2], t1 = t4[lane * 2 + 1];

    __align__(16) __nv_bfloat162 sb[4];
    __align__(16) __nv_bfloat162 tb[4];
    sb[0] = __floats2bfloat162_rn(s0.x, s0.y);
    sb[1] = __floats2bfloat162_rn(s0.z, s0.w);
    sb[2] = __floats2bfloat162_rn(s1.x, s1.y);
    sb[3] = __floats2bfloat162_rn(s1.z, s1.w);
    tb[0] = __floats2bfloat162_rn(t0.x, t0.y);
    tb[1] = __floats2bfloat162_rn(t0.z, t0.w);
    tb[2] = __floats2bfloat162_rn(t1.x, t1.y);
    tb[3] = __floats2bfloat162_rn(t1.z, t1.w);
    *(uint4*)&g_Abf[(size_t)row * DD + lane * 8] = *(const uint4*)sb;
    *(uint4*)&g_Bbf[(size_t)row * DD + lane * 8] = *(const uint4*)tb;

    const int d0 = lane * 8;
    atomicAdd(&sh_tall[d0 + 0], t0.x); atomicAdd(&sh_tall[d0 + 1], t0.y);
    atomicAdd(&sh_tall[d0 + 2], t0.z); atomicAdd(&sh_tall[d0 + 3], t0.w);
    atomicAdd(&sh_tall[d0 + 4], t1.x); atomicAdd(&sh_tall[d0 + 5], t1.y);
    atomicAdd(&sh_tall[d0 + 6], t1.z); atomicAdd(&sh_tall[d0 + 7], t1.w);

    float dot = s0.x * t0.x + s0.y * t0.y + s0.z * t0.z + s0.w * t0.w
              + s1.x * t1.x + s1.y * t1.y + s1.z * t1.z + s1.w * t1.w;
    #pragma unroll
    for (int o = 16; o > 0; o >>= 1)
        dot += __shfl_xor_sync(0xffffffffu, dot, o);

    if (lane == 0) {
        g_diag[row] = dot;
        int id = ids[row];
        int pos = g_off[id] + atomicAdd(&g_fill[id], 1);
        g_perm[pos] = row;
    }
    __syncthreads();
    if (tid < DD) atomicAdd(&g_Tall[tid], sh_tall[tid]);
}

// ---------------- PTX helpers ----------------
__device__ __forceinline__ uint32_t smem_u32(const void* p) {
    uint32_t a;
    asm("{ .reg .u64 t; cvta.to.shared.u64 t, %1; cvt.u32.u64 %0, t; }"
        : "=r"(a) : "l"(p));
    return a;
}
__device__ __forceinline__ void cp16(uint32_t dst, const void* src) {
    asm volatile("cp.async.cg.shared.global [%0], [%1], 16;" :: "r"(dst), "l"(src));
}
__device__ __forceinline__ void ldsm_x4(uint32_t* r, uint32_t addr) {
    asm volatile("ldmatrix.sync.aligned.m8n8.x4.shared.b16 {%0,%1,%2,%3}, [%4];"
                 : "=r"(r[0]), "=r"(r[1]), "=r"(r[2]), "=r"(r[3]) : "r"(addr));
}
__device__ __forceinline__ void mma16816(float* d, const uint32_t* a, const uint32_t* b) {
    asm volatile(
        "mma.sync.aligned.m16n8k16.row.col.f32.bf16.bf16.f32 "
        "{%0,%1,%2,%3}, {%4,%5,%6,%7}, {%8,%9}, {%0,%1,%2,%3};"
        : "+f"(d[0]), "+f"(d[1]), "+f"(d[2]), "+f"(d[3])
        : "r"(a[0]), "r"(a[1]), "r"(a[2]), "r"(a[3]), "r"(b[0]), "r"(b[1]));
}

// ---------------- species kernel smem layout (rows of 512B, swizzled) --------
// byte offset of 16B chunk c (0..31) in row r: r*512 + ((c<<4) ^ ((r&7)<<4))
constexpr int AB_OFF    = 0;                       // CAP*512 = 98304
constexpr int BB_OFF    = CAP * 512;               // 98304..196608
constexpr int IDX_OFF   = 2 * CAP * 512;           // 192 ints
constexpr int REXP_OFF  = IDX_OFF + 768;
constexpr int CEXP_OFF  = REXP_OFF + 768;
constexpr int RSAME_OFF = CEXP_OFF + 768;
constexpr int TALL_OFF  = RSAME_OFF + 768;         // 256 floats
constexpr int RED_OFF   = TALL_OFF + 1024;         // 32 floats scratch
constexpr int SMEM_SP   = RED_OFF + 256;           // ~201.4 KB

// ---------------- species: one block = one species, everything fused ---------
__global__ void __launch_bounds__(256)
species_kernel(float* __restrict__ out) {
    const int c = blockIdx.x;
    const int n_c = g_cnti[c];
    const int o   = g_off[c];
    const int nst = (n_c + 63) >> 6;
    const int nrows = nst * 64;

    extern __shared__ char smem[];
    const uint32_t sb = smem_u32(smem);
    int*   s_idx   = (int*)(smem + IDX_OFF);
    float* s_rexp  = (float*)(smem + REXP_OFF);
    float* s_cexp  = (float*)(smem + CEXP_OFF);
    float* s_rsame = (float*)(smem + RSAME_OFF);
    float* s_tall  = (float*)(smem + TALL_OFF);
    float* s_red   = (float*)(smem + RED_OFF);
    __shared__ bool sh_last;

    const int tid  = threadIdx.x;
    const int wid  = tid >> 5;
    const int lane = tid & 31;
    const int wg   = wid >> 2;       // tile group 0/1
    const int wid4 = wid & 3;

    if (tid < CAP) { s_rexp[tid] = 0.f; s_cexp[tid] = 0.f; s_rsame[tid] = 0.f; }
    for (int r = tid; r < nrows; r += 256)
        s_idx[r] = g_perm[o + min(r, n_c - 1)];
    __syncthreads();

    if (n_c > 0) {
        // ---- load all species rows (A=S, B=T) + Tall ----
        if (tid < 64) cp16(sb + TALL_OFF + tid * 16, &g_Tall[tid * 4]);
        for (int j = tid; j < nrows * 32; j += 256) {
            int r = j >> 5, ch = j & 31;
            uint32_t d = (uint32_t)(r * 512) + (uint32_t)(((ch << 4) ^ ((r & 7) << 4)));
            const size_t src = (size_t)s_idx[r] * DD + ch * 8;
            cp16(sb + AB_OFF + d, &g_Abf[src]);
            cp16(sb + BB_OFF + d, &g_Bbf[src]);
        }
        asm volatile("cp.async.commit_group;");
        asm volatile("cp.async.wait_group 0;" ::: "memory");
        __syncthreads();

        // ---- tiles: 64x64, two 4-warp groups in parallel ----
        const int ntiles = nst * nst;
        for (int t = wg; t < ntiles; t += 2) {
            const int mt = t / nst;
            const int nt = t % nst;
            const int mrem = n_c - mt * 64;
            const int nrem = n_c - nt * 64;

            // A fragment addressing
            const int ra = mt * 64 + wid4 * 16 + (lane & 15);
            const uint32_t aRow = sb + AB_OFF + ra * 512;
            const uint32_t aX   = (uint32_t)((ra & 7) << 4);
            const uint32_t aQ   = (uint32_t)((lane >> 4) << 4);
            // B fragment addressing
            uint32_t bRow[4], bX[4];
            #pragma unroll
            for (int np = 0; np < 4; np++) {
                int rb = nt * 64 + np * 16 + ((lane >> 4) & 1) * 8 + (lane & 7);
                bRow[np] = sb + BB_OFF + rb * 512;
                bX[np]   = (uint32_t)((rb & 7) << 4);
            }
            const uint32_t bQ = (uint32_t)(((lane >> 3) & 1) << 4);

            float acc[8][4];
            #pragma unroll
            for (int n2 = 0; n2 < 8; n2++)
                #pragma unroll
                for (int cc2 = 0; cc2 < 4; cc2++) acc[n2][cc2] = 0.f;

            #pragma unroll
            for (int ks = 0; ks < 16; ks++) {
                const uint32_t kb = (uint32_t)(ks * 32);
                uint32_t a[4], b[8][2];
                ldsm_x4(a, aRow + ((kb + aQ) ^ aX));
                #pragma unroll
                for (int np = 0; np < 4; np++)
                    ldsm_x4(&b[2 * np][0], bRow[np] + ((kb + bQ) ^ bX[np]));
                #pragma unroll
                for (int n2 = 0; n2 < 8; n2++)
                    mma16816(acc[n2], a, b[n2]);
            }

            // epilogue: all pairs same-species; diag patch at rloc==cloc
            #pragma unroll
            for (int h = 0; h < 2; h++) {
                const int rloc = mt * 64 + wid4 * 16 + (lane >> 2) + 8 * h;
                const bool rvalid = (rloc - mt * 64) < mrem;
                const float dval = rvalid ? g_diag[s_idx[rloc]] : 0.f;
                float re = 0.f, rsm = 0.f;
                #pragma unroll
                for (int n2 = 0; n2 < 8; n2++) {
                    #pragma unroll
                    for (int cc2 = 0; cc2 < 2; cc2++) {
                        int cloc = nt * 64 + n2 * 8 + (lane & 3) * 2 + cc2;
                        if (rvalid && (cloc - nt * 64) < nrem) {
                            float s = acc[n2][2 * h + cc2];
                            if (rloc == cloc) s = dval;
                            rsm += s;
                            float e = __expf((s - 1.0f) * INV_TAU);
                            re += e;
                            atomicAdd(&s_cexp[cloc], e);
                        }
                    }
                }
                if (rvalid) {
                    atomicAdd(&s_rexp[rloc], re);
                    atomicAdd(&s_rsame[rloc], rsm);
                }
            }
        }
    }
    __syncthreads();

    // ---- per-row finalize: rowsum dot + CE + triplet ----
    float seg = 0.f, trv = 0.f, trn = 0.f;
    if (tid < n_c) {
        const int r = tid;
        // rsum = dot(bf16 S row, Tall)
        float rsum = 0.f;
        const uint32_t rx = (uint32_t)((r & 7) << 4);
        #pragma unroll
        for (int ch = 0; ch < 32; ch++) {
            uint4 v = *(const uint4*)(smem + AB_OFF + r * 512
                                      + (((uint32_t)(ch << 4)) ^ rx));
            const __nv_bfloat162* p = (const __nv_bfloat162*)&v;
            #pragma unroll
            for (int i = 0; i < 4; i++) {
                float2 f2 = __bfloat1622float2(p[i]);
                rsum += f2.x * s_tall[ch * 8 + 2 * i]
                      + f2.y * s_tall[ch * 8 + 2 * i + 1];
            }
        }
        const float dg = g_diag[s_idx[r]];
        const float dl = dg * INV_TAU;
        seg = __logf(s_rexp[r]) + __logf(s_cexp[r]) + 2.0f * (INV_TAU - dl);

        const float cnt = (float)n_c;
        const float pos_cnt = cnt - 1.0f;
        const float neg_cnt = (float)BN - cnt;
        const float pos_mean = (s_rsame[r] - dg) / fmaxf(pos_cnt, 1.0f);
        const float neg_mean = (rsum - s_rsame[r]) / fmaxf(neg_cnt, 1.0f);
        const float tri = fmaxf(neg_mean - pos_mean + MARGIN, 0.0f);
        const bool valid = (pos_cnt > 0.0f) && (neg_cnt > 0.0f);
        trv = valid ? tri : 0.0f;
        trn = valid ? 1.0f : 0.0f;
    }
    #pragma unroll
    for (int ofs = 16; ofs > 0; ofs >>= 1) {
        seg += __shfl_xor_sync(0xffffffffu, seg, ofs);
        trv += __shfl_xor_sync(0xffffffffu, trv, ofs);
        trn += __shfl_xor_sync(0xffffffffu, trn, ofs);
    }
    if (lane == 0) {
        s_red[wid] = seg; s_red[8 + wid] = trv; s_red[16 + wid] = trn;
    }
    __syncthreads();
    if (tid == 0) {
        float segs = 0.f, trvs = 0.f, trns = 0.f;
        #pragma unroll
        for (int w = 0; w < 8; w++) {
            segs += s_red[w]; trvs += s_red[8 + w]; trns += s_red[16 + w];
        }
        bool valid_s = (n_c >= 2);
        g_per[c]  = valid_s ? segs / (2.0f * (float)n_c) : 0.0f;
        g_pern[c] = valid_s ? 1.0f : 0.0f;
        g_triv[c] = trvs;
        g_trin[c] = trns;
        __threadfence();
        sh_last = (atomicAdd(&g_done, 1) == NS - 1);
    }
    __syncthreads();
    if (!sh_last) return;
    __threadfence();

    // ---- last block: combine 64 species ----
    float p = 0.f, pn = 0.f, tv = 0.f, tn = 0.f;
    if (tid < NS) {
        p  = g_per[tid];  pn = g_pern[tid];
        tv = g_triv[tid]; tn = g_trin[tid];
    }
    #pragma unroll
    for (int ofs = 16; ofs > 0; ofs >>= 1) {
        p  += __shfl_xor_sync(0xffffffffu, p,  ofs);
        pn += __shfl_xor_sync(0xffffffffu, pn, ofs);
        tv += __shfl_xor_sync(0xffffffffu, tv, ofs);
        tn += __shfl_xor_sync(0xffffffffu, tn, ofs);
    }
    if (lane == 0) {
        s_red[wid] = p; s_red[8 + wid] = pn;
        s_red[16 + wid] = tv; s_red[24 + wid] = tn;
    }
    __syncthreads();
    if (tid == 0) {
        float ps = 0.f, pns = 0.f, tvs = 0.f, tns = 0.f;
        #pragma unroll
        for (int w = 0; w < 8; w++) {
            ps += s_red[w]; pns += s_red[8 + w];
            tvs += s_red[16 + w]; tns += s_red[24 + w];
        }
        out[0] = ps / fmaxf(pns, 1.0f) + tvs / fmaxf(tns, 1.0f);
    }
}

extern "C" void kernel_launch(void* const* d_in, const int* in_sizes, int n_in,
                              void* d_out, int out_size) {
    const float* species = (const float*)d_in[0];
    const float* text    = (const float*)d_in[1];
    const int*   ids     = (const int*)d_in[2];
    float* out = (float*)d_out;

    cudaFuncSetAttribute(species_kernel,
                         cudaFuncAttributeMaxDynamicSharedMemorySize, SMEM_SP);

    setup_kernel<<<1, 1024>>>(ids);
    prep_kernel<<<BN / 8, 256>>>(species, text, ids);
    species_kernel<<<NS, 256, SMEM_SP>>>(out);
}

// round 16
// speedup vs baseline: 1.4559x; 1.4559x over previous
#include <cuda_runtime.h>
#include <cuda_bf16.h>
#include <math.h>
#include <stdint.h>

// ---------------- problem constants ----------------
constexpr int   BN      = 8192;
constexpr int   DD      = 256;
constexpr int   NS      = 64;
constexpr float INV_TAU = 1.0f / 0.07f;
constexpr float MARGIN  = 0.2f;

// ---------------- device scratch ----------------
__device__ __align__(16) __nv_bfloat16 g_Abf[(size_t)BN * DD];
__device__ __align__(16) __nv_bfloat16 g_Bbf[(size_t)BN * DD];

__device__ float g_rowexp[BN];
__device__ float g_colexp[BN];
__device__ float g_rowsum[BN];
__device__ float g_rowsame[BN];
__device__ float g_diag[BN];
__device__ int   g_cnti[NS];
__device__ int   g_off[NS];
__device__ int   g_fill[NS];
__device__ int   g_perm[BN];
__device__ float g_Tall[DD];

__device__ int   g_sdone[NS];  // per-species tile-block completion
__device__ float g_per[NS];    // per-species infonce contribution
__device__ float g_pern[NS];
__device__ float g_triv[NS];
__device__ float g_trin[NS];
__device__ int   g_done;       // species-finalizer completion
__device__ int   g_nact;       // number of non-empty species

// ---------------- setup: histogram + offsets + zero (1 block) ----------------
__global__ void setup_kernel(const int* __restrict__ ids) {
    __shared__ int hist[NS];
    const int tid = threadIdx.x;         // 1024 threads
    if (tid < NS) hist[tid] = 0;
    __syncthreads();
    #pragma unroll
    for (int t = 0; t < BN / 1024; t++)
        atomicAdd(&hist[ids[tid + t * 1024]], 1);
    __syncthreads();
    if (tid == 0) {
        int run = 0, nact = 0;
        for (int c = 0; c < NS; c++) {
            g_off[c] = run;
            int h = hist[c];
            g_cnti[c] = h;
            run += h;
            if (h > 0) nact++;
        }
        g_done = 0;
        g_nact = nact;
    }
    if (tid < NS) {
        g_fill[tid]  = 0;
        g_sdone[tid] = 0;
        g_per[tid]  = 0.f; g_pern[tid] = 0.f;
        g_triv[tid] = 0.f; g_trin[tid] = 0.f;
    }
    if (tid < DD) g_Tall[tid] = 0.f;
}

// ---------------- prep: fp32->bf16, exact diag, scatter, Tall, zero stats -----
__global__ void prep_kernel(const float* __restrict__ S,
                            const float* __restrict__ T,
                            const int* __restrict__ ids) {
    __shared__ float sh_tall[DD];
    const int tid  = threadIdx.x;
    const int warp = tid >> 5;
    const int lane = tid & 31;
    const int row  = blockIdx.x * 8 + warp;
    if (tid < DD) sh_tall[tid] = 0.f;
    __syncthreads();

    const float4* s4 = (const float4*)(S + (size_t)row * DD);
    const float4* t4 = (const float4*)(T + (size_t)row * DD);
    float4 s0 = s4[lane * 2], s1 = s4[lane * 2 + 1];
    float4 t0 = t4[lane * 2], t1 = t4[lane * 2 + 1];

    __align__(16) __nv_bfloat162 sb[4];
    __align__(16) __nv_bfloat162 tb[4];
    sb[0] = __floats2bfloat162_rn(s0.x, s0.y);
    sb[1] = __floats2bfloat162_rn(s0.z, s0.w);
    sb[2] = __floats2bfloat162_rn(s1.x, s1.y);
    sb[3] = __floats2bfloat162_rn(s1.z, s1.w);
    tb[0] = __floats2bfloat162_rn(t0.x, t0.y);
    tb[1] = __floats2bfloat162_rn(t0.z, t0.w);
    tb[2] = __floats2bfloat162_rn(t1.x, t1.y);
    tb[3] = __floats2bfloat162_rn(t1.z, t1.w);
    *(uint4*)&g_Abf[(size_t)row * DD + lane * 8] = *(const uint4*)sb;
    *(uint4*)&g_Bbf[(size_t)row * DD + lane * 8] = *(const uint4*)tb;

    const int d0 = lane * 8;
    atomicAdd(&sh_tall[d0 + 0], t0.x); atomicAdd(&sh_tall[d0 + 1], t0.y);
    atomicAdd(&sh_tall[d0 + 2], t0.z); atomicAdd(&sh_tall[d0 + 3], t0.w);
    atomicAdd(&sh_tall[d0 + 4], t1.x); atomicAdd(&sh_tall[d0 + 5], t1.y);
    atomicAdd(&sh_tall[d0 + 6], t1.z); atomicAdd(&sh_tall[d0 + 7], t1.w);

    float dot = s0.x * t0.x + s0.y * t0.y + s0.z * t0.z + s0.w * t0.w
              + s1.x * t1.x + s1.y * t1.y + s1.z * t1.z + s1.w * t1.w;
    #pragma unroll
    for (int o = 16; o > 0; o >>= 1)
        dot += __shfl_xor_sync(0xffffffffu, dot, o);

    if (lane == 0) {
        g_diag[row] = dot;
        g_rowexp[row]  = 0.f;
        g_colexp[row]  = 0.f;
        g_rowsame[row] = 0.f;
        int id = ids[row];
        int pos = g_off[id] + atomicAdd(&g_fill[id], 1);
        g_perm[pos] = row;
    }
    __syncthreads();
    if (tid < DD) atomicAdd(&g_Tall[tid], sh_tall[tid]);
}

// ---------------- PTX helpers ----------------
__device__ __forceinline__ uint32_t smem_u32(const void* p) {
    uint32_t a;
    asm("{ .reg .u64 t; cvta.to.shared.u64 t, %1; cvt.u32.u64 %0, t; }"
        : "=r"(a) : "l"(p));
    return a;
}
__device__ __forceinline__ void cp16(uint32_t dst, const void* src) {
    asm volatile("cp.async.cg.shared.global [%0], [%1], 16;" :: "r"(dst), "l"(src));
}
template<int N> __device__ __forceinline__ void cp_wait() {
    asm volatile("cp.async.wait_group %0;" :: "n"(N) : "memory");
}
__device__ __forceinline__ void ldsm_x4(uint32_t* r, uint32_t addr) {
    asm volatile("ldmatrix.sync.aligned.m8n8.x4.shared.b16 {%0,%1,%2,%3}, [%4];"
                 : "=r"(r[0]), "=r"(r[1]), "=r"(r[2]), "=r"(r[3]) : "r"(addr));
}
__device__ __forceinline__ void mma16816(float* d, const uint32_t* a, const uint32_t* b) {
    asm volatile(
        "mma.sync.aligned.m16n8k16.row.col.f32.bf16.bf16.f32 "
        "{%0,%1,%2,%3}, {%4,%5,%6,%7}, {%8,%9}, {%0,%1,%2,%3};"
        : "+f"(d[0]), "+f"(d[1]), "+f"(d[2]), "+f"(d[3])
        : "r"(a[0]), "r"(a[1]), "r"(a[2]), "r"(a[3]), "r"(b[0]), "r"(b[1]));
}
// SW128 swizzle within a [64 rows x 128B] chunk
__device__ __forceinline__ uint32_t swz(int r, int q) {
    return (uint32_t)(r * 128 + ((q ^ (r & 7)) << 4));
}

// blockexp smem layout (dynamic)
constexpr int SB_OFF    = 32768;
constexpr int RA_OFF    = 65536;               // 64 ints
constexpr int RB_OFF    = RA_OFF + 256;        // 64 ints
constexpr int REXP_OFF  = RB_OFF + 256;        // 64 floats
constexpr int CEXP_OFF  = REXP_OFF + 256;      // 64 floats
constexpr int RSAME_OFF = CEXP_OFF + 256;      // 64 floats
constexpr int TALL_OFF  = RSAME_OFF + 256;     // 256 floats
constexpr int RED_OFF   = TALL_OFF + 1024;     // 16 floats scratch
constexpr int SMEM_BE   = RED_OFF + 64;        // ~67.9 KB

// ---------------- blockexp: tiles + per-species finalize + combine -----------
// grid: (9, NS) — tiles (mt,nt) in up-to-3x3; 128 threads (4 warps)
__global__ void __launch_bounds__(128)
blockexp_kernel(float* __restrict__ out) {
    const int c  = blockIdx.y;
    const int x  = blockIdx.x;
    const int mt = x / 3;
    const int nt = x % 3;
    const int n_c = g_cnti[c];
    if (mt * 64 >= n_c || nt * 64 >= n_c) return;
    const int o = g_off[c];
    const int nst = (n_c + 63) >> 6;
    const int mrem = n_c - mt * 64;
    const int nrem = n_c - nt * 64;

    extern __shared__ char smem[];
    const uint32_t sbase = smem_u32(smem);
    int*   s_ra    = (int*)(smem + RA_OFF);
    int*   s_rb    = (int*)(smem + RB_OFF);
    float* s_rexp  = (float*)(smem + REXP_OFF);
    float* s_cexp  = (float*)(smem + CEXP_OFF);
    float* s_rsame = (float*)(smem + RSAME_OFF);
    float* s_tall  = (float*)(smem + TALL_OFF);
    float* s_red   = (float*)(smem + RED_OFF);
    __shared__ int sh_ticket;
    __shared__ bool sh_lastall;

    const int tid  = threadIdx.x;
    const int wid  = tid >> 5;
    const int lane = tid & 31;

    if (tid < 64) {
        int r = mt * 64 + tid;
        s_ra[tid] = g_perm[o + min(r, n_c - 1)];
        s_rexp[tid] = 0.f; s_rsame[tid] = 0.f;
    } else {
        int t = tid - 64;
        int r = nt * 64 + t;
        s_rb[t] = g_perm[o + min(r, n_c - 1)];
        s_cexp[t] = 0.f;
    }
    __syncthreads();

    // gather load, two commit groups (K-chunks 0-1, then 2-3); Tall in group 0
    if (nt == 0 && tid < 64)
        cp16(sbase + TALL_OFF + tid * 16, &g_Tall[tid * 4]);
    #pragma unroll
    for (int g = 0; g < 2; g++) {
        #pragma unroll
        for (int h = 0; h < 8; h++) {
            int f  = tid + h * 128;          // 0..1023
            int r  = f >> 4;                 // 0..63
            int qq = f & 15;                 // 0..15
            int kc = g * 2 + (qq >> 3);
            int q7 = qq & 7;
            uint32_t sw = (uint32_t)(kc * 8192) + swz(r, q7);
            cp16(sbase + sw,
                 &g_Abf[(size_t)s_ra[r] * DD + kc * 64 + q7 * 8]);
            cp16(sbase + SB_OFF + sw,
                 &g_Bbf[(size_t)s_rb[r] * DD + kc * 64 + q7 * 8]);
        }
        asm volatile("cp.async.commit_group;");
    }

    // fragment base offsets (within a chunk); addr(ks) = base ^ ((ks&3)<<5)
    uint32_t aD, bD[4];
    aD = swz(wid * 16 + (lane & 15), lane >> 4);
    #pragma unroll
    for (int np = 0; np < 4; np++)
        bD[np] = swz(np * 16 + ((lane >> 4) & 1) * 8 + (lane & 7),
                     (lane >> 3) & 1);

    float acc[8][4];
    #pragma unroll
    for (int nt2 = 0; nt2 < 8; nt2++)
        #pragma unroll
        for (int cc = 0; cc < 4; cc++) acc[nt2][cc] = 0.f;

    cp_wait<1>();
    __syncthreads();
    #pragma unroll
    for (int ks = 0; ks < 8; ks++) {
        const uint32_t base = sbase + (uint32_t)((ks >> 2) * 8192);
        const uint32_t kx   = (uint32_t)(ks & 3) << 5;
        uint32_t a[4], b[8][2];
        ldsm_x4(a, base + (aD ^ kx));
        #pragma unroll
        for (int np = 0; np < 4; np++)
            ldsm_x4(&b[2 * np][0], base + SB_OFF + (bD[np] ^ kx));
        #pragma unroll
        for (int nt2 = 0; nt2 < 8; nt2++)
            mma16816(acc[nt2], a, b[nt2]);
    }
    cp_wait<0>();
    __syncthreads();
    #pragma unroll
    for (int ks = 8; ks < 16; ks++) {
        const uint32_t base = sbase + (uint32_t)((ks >> 2) * 8192);
        const uint32_t kx   = (uint32_t)(ks & 3) << 5;
        uint32_t a[4], b[8][2];
        ldsm_x4(a, base + (aD ^ kx));
        #pragma unroll
        for (int np = 0; np < 4; np++)
            ldsm_x4(&b[2 * np][0], base + SB_OFF + (bD[np] ^ kx));
        #pragma unroll
        for (int nt2 = 0; nt2 < 8; nt2++)
            mma16816(acc[nt2], a, b[nt2]);
    }

    // ---- rsum for this tile's A-rows (nt==0 tiles only): dot(bf16 row, Tall)
    if (nt == 0) {
        const int r  = tid >> 1;
        const int hf = tid & 1;
        float partial = 0.f;
        #pragma unroll
        for (int cell = 0; cell < 16; cell++) {
            int d0 = hf * 128 + cell * 8;
            int kc = d0 >> 6;
            int q7 = (d0 & 63) >> 3;
            uint4 v = *(const uint4*)(smem + kc * 8192 + swz(r, q7));
            const __nv_bfloat162* p = (const __nv_bfloat162*)&v;
            #pragma unroll
            for (int i = 0; i < 4; i++) {
                float2 f2 = __bfloat1622float2(p[i]);
                partial += f2.x * s_tall[d0 + 2 * i]
                         + f2.y * s_tall[d0 + 2 * i + 1];
            }
        }
        partial += __shfl_xor_sync(0xffffffffu, partial, 1);
        if (hf == 0 && r < mrem) g_rowsum[s_ra[r]] = partial;
    }

    // epilogue: exp + raw sums over valid same-species elements, exact diag
    #pragma unroll
    for (int h = 0; h < 2; h++) {
        const int rloc = wid * 16 + (lane >> 2) + 8 * h;
        const bool rvalid = rloc < mrem;
        const int gr = s_ra[rloc];
        const float dval = g_diag[gr];
        float re = 0.f, rsm = 0.f;
        #pragma unroll
        for (int nt2 = 0; nt2 < 8; nt2++) {
            #pragma unroll
            for (int cc = 0; cc < 2; cc++) {
                int cloc = nt2 * 8 + (lane & 3) * 2 + cc;
                if (rvalid && cloc < nrem) {
                    float s = acc[nt2][2 * h + cc];
                    if (gr == s_rb[cloc]) s = dval;
                    rsm += s;
                    float e = __expf((s - 1.0f) * INV_TAU);
                    re += e;
                    atomicAdd(&s_cexp[cloc], e);
                }
            }
        }
        if (rvalid) {
            atomicAdd(&s_rexp[rloc], re);
            atomicAdd(&s_rsame[rloc], rsm);
        }
    }
    __syncthreads();

    if (tid < 64) {
        if (tid < mrem) {
            atomicAdd(&g_rowexp[s_ra[tid]],  s_rexp[tid]);
            atomicAdd(&g_rowsame[s_ra[tid]], s_rsame[tid]);
        }
    } else {
        int t = tid - 64;
        if (t < nrem) atomicAdd(&g_colexp[s_rb[t]], s_cexp[t]);
    }

    // ---- per-species completion ticket ----
    __threadfence();
    __syncthreads();
    if (tid == 0) sh_ticket = atomicAdd(&g_sdone[c], 1);
    __syncthreads();
    if (sh_ticket != nst * nst - 1) return;
    __threadfence();

    // ---- species finalize (last tile-block of species c) ----
    float seg = 0.f, trv = 0.f, trn = 0.f;
    for (int r = tid; r < n_c; r += 128) {
        const int row = g_perm[o + r];
        const float dg = g_diag[row];
        const float dl = dg * INV_TAU;
        seg += __logf(g_rowexp[row]) + __logf(g_colexp[row])
             + 2.0f * (INV_TAU - dl);

        const float cnt = (float)n_c;
        const float pos_cnt = cnt - 1.0f;
        const float neg_cnt = (float)BN - cnt;
        const float rsame = g_rowsame[row];
        const float pos_mean = (rsame - dg) / fmaxf(pos_cnt, 1.0f);
        const float neg_mean = (g_rowsum[row] - rsame) / fmaxf(neg_cnt, 1.0f);
        const float tri = fmaxf(neg_mean - pos_mean + MARGIN, 0.0f);
        const bool valid = (pos_cnt > 0.0f) && (neg_cnt > 0.0f);
        trv += valid ? tri : 0.0f;
        trn += valid ? 1.0f : 0.0f;
    }
    #pragma unroll
    for (int ofs = 16; ofs > 0; ofs >>= 1) {
        seg += __shfl_xor_sync(0xffffffffu, seg, ofs);
        trv += __shfl_xor_sync(0xffffffffu, trv, ofs);
        trn += __shfl_xor_sync(0xffffffffu, trn, ofs);
    }
    if (lane == 0) {
        s_red[wid] = seg; s_red[4 + wid] = trv; s_red[8 + wid] = trn;
    }
    __syncthreads();
    if (tid == 0) {
        float segs = s_red[0] + s_red[1] + s_red[2] + s_red[3];
        float trvs = s_red[4] + s_red[5] + s_red[6] + s_red[7];
        float trns = s_red[8] + s_red[9] + s_red[10] + s_red[11];
        bool valid_s = (n_c >= 2);
        g_per[c]  = valid_s ? segs / (2.0f * (float)n_c) : 0.0f;
        g_pern[c] = valid_s ? 1.0f : 0.0f;
        g_triv[c] = trvs;
        g_trin[c] = trns;
        __threadfence();
        sh_lastall = (atomicAdd(&g_done, 1) == g_nact - 1);
    }
    __syncthreads();
    if (!sh_lastall) return;
    __threadfence();

    // ---- overall-last block: combine 64 species ----
    float p = 0.f, pn = 0.f, tv = 0.f, tn = 0.f;
    if (tid < NS) {
        p  = g_per[tid];  pn = g_pern[tid];
        tv = g_triv[tid]; tn = g_trin[tid];
    }
    #pragma unroll
    for (int ofs = 16; ofs > 0; ofs >>= 1) {
        p  += __shfl_xor_sync(0xffffffffu, p,  ofs);
        pn += __shfl_xor_sync(0xffffffffu, pn, ofs);
        tv += __shfl_xor_sync(0xffffffffu, tv, ofs);
        tn += __shfl_xor_sync(0xffffffffu, tn, ofs);
    }
    if (lane == 0 && wid < 2) {
        s_red[wid] = p; s_red[4 + wid] = pn;
        s_red[8 + wid] = tv; s_red[12 + wid] = tn;
    }
    __syncthreads();
    if (tid == 0) {
        float ps  = s_red[0] + s_red[1];
        float pns = s_red[4] + s_red[5];
        float tvs = s_red[8] + s_red[9];
        float tns = s_red[12] + s_red[13];
        out[0] = ps / fmaxf(pns, 1.0f) + tvs / fmaxf(tns, 1.0f);
    }
}

extern "C" void kernel_launch(void* const* d_in, const int* in_sizes, int n_in,
                              void* d_out, int out_size) {
    const float* species = (const float*)d_in[0];
    const float* text    = (const float*)d_in[1];
    const int*   ids     = (const int*)d_in[2];
    float* out = (float*)d_out;

    cudaFuncSetAttribute(blockexp_kernel,
                         cudaFuncAttributeMaxDynamicSharedMemorySize, SMEM_BE);

    setup_kernel<<<1, 1024>>>(ids);
    prep_kernel<<<BN / 8, 256>>>(species, text, ids);
    blockexp_kernel<<<dim3(9, NS), 128, SMEM_BE>>>(out);
}

// round 17
// speedup vs baseline: 1.9361x; 1.3298x over previous
#include <cuda_runtime.h>
#include <cuda_bf16.h>
#include <math.h>
#include <stdint.h>

// ---------------- problem constants ----------------
constexpr int   BN      = 8192;
constexpr int   DD      = 256;
constexpr int   NS      = 64;
constexpr float INV_TAU = 1.0f / 0.07f;
constexpr float MARGIN  = 0.2f;
constexpr int   CAP     = 192;     // slots per species (mean 128, ~6 sigma)

// ---------------- device scratch (zero-initialized at load; self-reset) ------
__device__ __align__(16) __nv_bfloat16 g_Abf[(size_t)BN * DD];
__device__ __align__(16) __nv_bfloat16 g_Bbf[(size_t)BN * DD];

__device__ float g_rowexp[BN];
__device__ float g_colexp[BN];
__device__ float g_rowsum[BN];
__device__ float g_rowsame[BN];
__device__ float g_diag[BN];
__device__ int   g_fill[NS];        // per-species row count (built by prep)
__device__ int   g_perm[NS * CAP];  // slot-packed row indices
__device__ float g_Tall[DD];

__device__ int   g_sdone[NS];       // per-species tile completion
__device__ float g_per[NS];
__device__ float g_pern[NS];
__device__ float g_triv[NS];
__device__ float g_trin[NS];
__device__ int   g_done;            // finalized-row count

// ---------------- prep: fp32->bf16, exact diag, slot scatter, Tall ------------
__global__ void prep_kernel(const float* __restrict__ S,
                            const float* __restrict__ T,
                            const int* __restrict__ ids) {
    __shared__ float sh_tall[DD];
    const int tid  = threadIdx.x;
    const int warp = tid >> 5;
    const int lane = tid & 31;
    const int row  = blockIdx.x * 8 + warp;
    if (tid < DD) sh_tall[tid] = 0.f;
    __syncthreads();

    const float4* s4 = (const float4*)(S + (size_t)row * DD);
    const float4* t4 = (const float4*)(T + (size_t)row * DD);
    float4 s0 = s4[lane * 2], s1 = s4[lane * 2 + 1];
    float4 t0 = t4[lane * 2], t1 = t4[lane * 2 + 1];

    __align__(16) __nv_bfloat162 sb[4];
    __align__(16) __nv_bfloat162 tb[4];
    sb[0] = __floats2bfloat162_rn(s0.x, s0.y);
    sb[1] = __floats2bfloat162_rn(s0.z, s0.w);
    sb[2] = __floats2bfloat162_rn(s1.x, s1.y);
    sb[3] = __floats2bfloat162_rn(s1.z, s1.w);
    tb[0] = __floats2bfloat162_rn(t0.x, t0.y);
    tb[1] = __floats2bfloat162_rn(t0.z, t0.w);
    tb[2] = __floats2bfloat162_rn(t1.x, t1.y);
    tb[3] = __floats2bfloat162_rn(t1.z, t1.w);
    *(uint4*)&g_Abf[(size_t)row * DD + lane * 8] = *(const uint4*)sb;
    *(uint4*)&g_Bbf[(size_t)row * DD + lane * 8] = *(const uint4*)tb;

    const int d0 = lane * 8;
    atomicAdd(&sh_tall[d0 + 0], t0.x); atomicAdd(&sh_tall[d0 + 1], t0.y);
    atomicAdd(&sh_tall[d0 + 2], t0.z); atomicAdd(&sh_tall[d0 + 3], t0.w);
    atomicAdd(&sh_tall[d0 + 4], t1.x); atomicAdd(&sh_tall[d0 + 5], t1.y);
    atomicAdd(&sh_tall[d0 + 6], t1.z); atomicAdd(&sh_tall[d0 + 7], t1.w);

    float dot = s0.x * t0.x + s0.y * t0.y + s0.z * t0.z + s0.w * t0.w
              + s1.x * t1.x + s1.y * t1.y + s1.z * t1.z + s1.w * t1.w;
    #pragma unroll
    for (int o = 16; o > 0; o >>= 1)
        dot += __shfl_xor_sync(0xffffffffu, dot, o);

    if (lane == 0) {
        g_diag[row] = dot;
        g_rowexp[row]  = 0.f;
        g_colexp[row]  = 0.f;
        g_rowsame[row] = 0.f;
        int id = ids[row];
        int pos = atomicAdd(&g_fill[id], 1);
        if (pos < CAP) g_perm[id * CAP + pos] = row;
    }
    __syncthreads();
    if (tid < DD) atomicAdd(&g_Tall[tid], sh_tall[tid]);
}

// ---------------- PTX helpers ----------------
__device__ __forceinline__ uint32_t smem_u32(const void* p) {
    uint32_t a;
    asm("{ .reg .u64 t; cvta.to.shared.u64 t, %1; cvt.u32.u64 %0, t; }"
        : "=r"(a) : "l"(p));
    return a;
}
__device__ __forceinline__ void cp16(uint32_t dst, const void* src) {
    asm volatile("cp.async.cg.shared.global [%0], [%1], 16;" :: "r"(dst), "l"(src));
}
template<int N> __device__ __forceinline__ void cp_wait() {
    asm volatile("cp.async.wait_group %0;" :: "n"(N) : "memory");
}
__device__ __forceinline__ void ldsm_x4(uint32_t* r, uint32_t addr) {
    asm volatile("ldmatrix.sync.aligned.m8n8.x4.shared.b16 {%0,%1,%2,%3}, [%4];"
                 : "=r"(r[0]), "=r"(r[1]), "=r"(r[2]), "=r"(r[3]) : "r"(addr));
}
__device__ __forceinline__ void mma16816(float* d, const uint32_t* a, const uint32_t* b) {
    asm volatile(
        "mma.sync.aligned.m16n8k16.row.col.f32.bf16.bf16.f32 "
        "{%0,%1,%2,%3}, {%4,%5,%6,%7}, {%8,%9}, {%0,%1,%2,%3};"
        : "+f"(d[0]), "+f"(d[1]), "+f"(d[2]), "+f"(d[3])
        : "r"(a[0]), "r"(a[1]), "r"(a[2]), "r"(a[3]), "r"(b[0]), "r"(b[1]));
}
// SW128 swizzle within a [64 rows x 128B] chunk
__device__ __forceinline__ uint32_t swz(int r, int q) {
    return (uint32_t)(r * 128 + ((q ^ (r & 7)) << 4));
}

// blockexp smem layout (dynamic)
constexpr int SB_OFF    = 32768;
constexpr int RA_OFF    = 65536;               // 64 ints
constexpr int RB_OFF    = RA_OFF + 256;        // 64 ints
constexpr int REXP_OFF  = RB_OFF + 256;
constexpr int CEXP_OFF  = REXP_OFF + 256;
constexpr int RSAME_OFF = CEXP_OFF + 256;
constexpr int TALL_OFF  = RSAME_OFF + 256;     // 256 floats
constexpr int RED_OFF   = TALL_OFF + 1024;     // 32 floats scratch
constexpr int SMEM_BE   = RED_OFF + 128;       // ~68 KB

// ---------------- blockexp: tiles + species finalize + combine + self-reset --
// grid: (9, NS) — tiles (mt,nt) in up-to-3x3; 256 threads (8 warps: 4m x 2n)
__global__ void __launch_bounds__(256)
blockexp_kernel(float* __restrict__ out) {
    const int c  = blockIdx.y;
    const int x  = blockIdx.x;
    const int mt = x / 3;
    const int nt = x % 3;
    const int n_c = min(g_fill[c], NS * 3);    // clamp to CAP range
    if (mt * 64 >= n_c || nt * 64 >= n_c) return;
    const int o = c * CAP;
    const int nst = (n_c + 63) >> 6;
    const int mrem = n_c - mt * 64;
    const int nrem = n_c - nt * 64;

    extern __shared__ char smem[];
    const uint32_t sbase = smem_u32(smem);
    int*   s_ra    = (int*)(smem + RA_OFF);
    int*   s_rb    = (int*)(smem + RB_OFF);
    float* s_rexp  = (float*)(smem + REXP_OFF);
    float* s_cexp  = (float*)(smem + CEXP_OFF);
    float* s_rsame = (float*)(smem + RSAME_OFF);
    float* s_tall  = (float*)(smem + TALL_OFF);
    float* s_red   = (float*)(smem + RED_OFF);
    __shared__ int sh_ticket;
    __shared__ bool sh_lastall;

    const int tid  = threadIdx.x;
    const int wid  = tid >> 5;
    const int lane = tid & 31;
    const int wm   = wid & 3;       // row group (16 rows)
    const int wn   = wid >> 2;      // col half (32 cols)

    if (tid < 64) {
        int r = mt * 64 + tid;
        s_ra[tid] = g_perm[o + min(r, n_c - 1)];
        s_rexp[tid] = 0.f; s_rsame[tid] = 0.f;
    } else if (tid < 128) {
        int t = tid - 64;
        int r = nt * 64 + t;
        s_rb[t] = g_perm[o + min(r, n_c - 1)];
        s_cexp[t] = 0.f;
    }
    __syncthreads();

    // gather load, two commit groups (K-chunks 0-1, then 2-3); Tall in group 0
    if (nt == 0 && tid < 64)
        cp16(sbase + TALL_OFF + tid * 16, &g_Tall[tid * 4]);
    #pragma unroll
    for (int g = 0; g < 2; g++) {
        #pragma unroll
        for (int h = 0; h < 4; h++) {
            int f  = tid + h * 256;          // 0..1023
            int r  = f >> 4;                 // 0..63
            int qq = f & 15;                 // 0..15
            int kc = g * 2 + (qq >> 3);
            int q7 = qq & 7;
            uint32_t sw = (uint32_t)(kc * 8192) + swz(r, q7);
            cp16(sbase + sw,
                 &g_Abf[(size_t)s_ra[r] * DD + kc * 64 + q7 * 8]);
            cp16(sbase + SB_OFF + sw,
                 &g_Bbf[(size_t)s_rb[r] * DD + kc * 64 + q7 * 8]);
        }
        asm volatile("cp.async.commit_group;");
    }

    // fragment base offsets; addr(ks) = base ^ ((ks&3)<<5), chunk (ks>>2)*8192
    const uint32_t aD = swz(wm * 16 + (lane & 15), lane >> 4);
    uint32_t bD[2];
    #pragma unroll
    for (int np = 0; np < 2; np++)
        bD[np] = swz(wn * 32 + np * 16 + ((lane >> 4) & 1) * 8 + (lane & 7),
                     (lane >> 3) & 1);

    float acc[4][4];
    #pragma unroll
    for (int n2 = 0; n2 < 4; n2++)
        #pragma unroll
        for (int cc = 0; cc < 4; cc++) acc[n2][cc] = 0.f;

    cp_wait<1>();
    __syncthreads();
    #pragma unroll
    for (int ks = 0; ks < 8; ks++) {
        const uint32_t base = sbase + (uint32_t)((ks >> 2) * 8192);
        const uint32_t kx   = (uint32_t)(ks & 3) << 5;
        uint32_t a[4], b[4][2];
        ldsm_x4(a, base + (aD ^ kx));
        #pragma unroll
        for (int np = 0; np < 2; np++)
            ldsm_x4(&b[2 * np][0], base + SB_OFF + (bD[np] ^ kx));
        #pragma unroll
        for (int n2 = 0; n2 < 4; n2++)
            mma16816(acc[n2], a, b[n2]);
    }
    cp_wait<0>();
    __syncthreads();
    #pragma unroll
    for (int ks = 8; ks < 16; ks++) {
        const uint32_t base = sbase + (uint32_t)((ks >> 2) * 8192);
        const uint32_t kx   = (uint32_t)(ks & 3) << 5;
        uint32_t a[4], b[4][2];
        ldsm_x4(a, base + (aD ^ kx));
        #pragma unroll
        for (int np = 0; np < 2; np++)
            ldsm_x4(&b[2 * np][0], base + SB_OFF + (bD[np] ^ kx));
        #pragma unroll
        for (int n2 = 0; n2 < 4; n2++)
            mma16816(acc[n2], a, b[n2]);
    }

    // ---- rsum for this tile's A-rows (nt==0): dot(bf16 row, Tall), 4 thr/row
    if (nt == 0) {
        const int r  = tid >> 2;         // 0..63
        const int qf = tid & 3;          // quarter of dims
        float partial = 0.f;
        #pragma unroll
        for (int cell = 0; cell < 8; cell++) {
            int d0 = qf * 64 + cell * 8;
            int kc = d0 >> 6;
            int q7 = (d0 & 63) >> 3;
            uint4 v = *(const uint4*)(smem + kc * 8192 + swz(r, q7));
            const __nv_bfloat162* p = (const __nv_bfloat162*)&v;
            #pragma unroll
            for (int i = 0; i < 4; i++) {
                float2 f2 = __bfloat1622float2(p[i]);
                partial += f2.x * s_tall[d0 + 2 * i]
                         + f2.y * s_tall[d0 + 2 * i + 1];
            }
        }
        partial += __shfl_xor_sync(0xffffffffu, partial, 1);
        partial += __shfl_xor_sync(0xffffffffu, partial, 2);
        if (qf == 0 && r < mrem) g_rowsum[s_ra[r]] = partial;
    }

    // epilogue: exp + raw sums over valid same-species elements, exact diag
    #pragma unroll
    for (int h = 0; h < 2; h++) {
        const int rloc = wm * 16 + (lane >> 2) + 8 * h;
        const bool rvalid = rloc < mrem;
        const int gr = s_ra[rloc];
        const float dval = g_diag[gr];
        float re = 0.f, rsm = 0.f;
        #pragma unroll
        for (int n2 = 0; n2 < 4; n2++) {
            #pragma unroll
            for (int cc = 0; cc < 2; cc++) {
                int cloc = wn * 32 + n2 * 8 + (lane & 3) * 2 + cc;
                if (rvalid && cloc < nrem) {
                    float s = acc[n2][2 * h + cc];
                    if (gr == s_rb[cloc]) s = dval;
                    rsm += s;
                    float e = __expf((s - 1.0f) * INV_TAU);
                    re += e;
                    atomicAdd(&s_cexp[cloc], e);
                }
            }
        }
        if (rvalid) {
            atomicAdd(&s_rexp[rloc], re);
            atomicAdd(&s_rsame[rloc], rsm);
        }
    }
    __syncthreads();

    if (tid < 64) {
        if (tid < mrem) {
            atomicAdd(&g_rowexp[s_ra[tid]],  s_rexp[tid]);
            atomicAdd(&g_rowsame[s_ra[tid]], s_rsame[tid]);
        }
    } else if (tid < 128) {
        int t = tid - 64;
        if (t < nrem) atomicAdd(&g_colexp[s_rb[t]], s_cexp[t]);
    }

    // ---- per-species completion ticket ----
    __threadfence();
    __syncthreads();
    if (tid == 0) sh_ticket = atomicAdd(&g_sdone[c], 1);
    __syncthreads();
    if (sh_ticket != nst * nst - 1) return;
    __threadfence();

    // ---- species finalize (last tile-block of species c) ----
    float seg = 0.f, trv = 0.f, trn = 0.f;
    for (int r = tid; r < n_c; r += 256) {
        const int row = g_perm[o + r];
        const float dg = g_diag[row];
        const float dl = dg * INV_TAU;
        seg += __logf(g_rowexp[row]) + __logf(g_colexp[row])
             + 2.0f * (INV_TAU - dl);

        const float cnt = (float)n_c;
        const float pos_cnt = cnt - 1.0f;
        const float neg_cnt = (float)BN - cnt;
        const float rsame = g_rowsame[row];
        const float pos_mean = (rsame - dg) / fmaxf(pos_cnt, 1.0f);
        const float neg_mean = (g_rowsum[row] - rsame) / fmaxf(neg_cnt, 1.0f);
        const float tri = fmaxf(neg_mean - pos_mean + MARGIN, 0.0f);
        const bool valid = (pos_cnt > 0.0f) && (neg_cnt > 0.0f);
        trv += valid ? tri : 0.0f;
        trn += valid ? 1.0f : 0.0f;
    }
    #pragma unroll
    for (int ofs = 16; ofs > 0; ofs >>= 1) {
        seg += __shfl_xor_sync(0xffffffffu, seg, ofs);
        trv += __shfl_xor_sync(0xffffffffu, trv, ofs);
        trn += __shfl_xor_sync(0xffffffffu, trn, ofs);
    }
    if (lane == 0) {
        s_red[wid] = seg; s_red[8 + wid] = trv; s_red[16 + wid] = trn;
    }
    __syncthreads();
    if (tid == 0) {
        float segs = 0.f, trvs = 0.f, trns = 0.f;
        #pragma unroll
        for (int w = 0; w < 8; w++) {
            segs += s_red[w]; trvs += s_red[8 + w]; trns += s_red[16 + w];
        }
        bool valid_s = (n_c >= 2);
        g_per[c]  = valid_s ? segs / (2.0f * (float)n_c) : 0.0f;
        g_pern[c] = valid_s ? 1.0f : 0.0f;
        g_triv[c] = trvs;
        g_trin[c] = trns;
        __threadfence();
        int prev = atomicAdd(&g_done, n_c);
        sh_lastall = (prev + n_c == BN);
    }
    __syncthreads();
    if (!sh_lastall) return;
    __threadfence();

    // ---- overall-last block: combine 64 species ----
    float p = 0.f, pn = 0.f, tv = 0.f, tn = 0.f;
    if (tid < NS) {
        p  = g_per[tid];  pn = g_pern[tid];
        tv = g_triv[tid]; tn = g_trin[tid];
    }
    #pragma unroll
    for (int ofs = 16; ofs > 0; ofs >>= 1) {
        p  += __shfl_xor_sync(0xffffffffu, p,  ofs);
        pn += __shfl_xor_sync(0xffffffffu, pn, ofs);
        tv += __shfl_xor_sync(0xffffffffu, tv, ofs);
        tn += __shfl_xor_sync(0xffffffffu, tn, ofs);
    }
    if (lane == 0 && wid < 2) {
        s_red[wid] = p; s_red[8 + wid] = pn;
        s_red[16 + wid] = tv; s_red[24 + wid] = tn;
    }
    __syncthreads();
    if (tid == 0) {
        float ps  = s_red[0] + s_red[1];
        float pns = s_red[8] + s_red[9];
        float tvs = s_red[16] + s_red[17];
        float tns = s_red[24] + s_red[25];
        out[0] = ps / fmaxf(pns, 1.0f) + tvs / fmaxf(tns, 1.0f);
    }

    // ---- self-reset for the next call (graph replay) ----
    if (tid < NS) { g_fill[tid] = 0; g_sdone[tid] = 0; }
    if (tid == 0) g_done = 0;
    if (tid < DD) g_Tall[tid] = 0.f;
}

extern "C" void kernel_launch(void* const* d_in, const int* in_sizes, int n_in,
                              void* d_out, int out_size) {
    const float* species = (const float*)d_in[0];
    const float* text    = (const float*)d_in[1];
    const int*   ids     = (const int*)d_in[2];
    float* out = (float*)d_out;

    cudaFuncSetAttribute(blockexp_kernel,
                         cudaFuncAttributeMaxDynamicSharedMemorySize, SMEM_BE);

    prep_kernel<<<BN / 8, 256>>>(species, text, ids);
    blockexp_kernel<<<dim3(9, NS), 256, SMEM_BE>>>(out);
}